// round 16
// baseline (speedup 1.0000x reference)
#include <cuda_runtime.h>
#include <cuda_fp16.h>
#include <cstdint>

// ---------------------------------------------------------------------------
// DisenGCN on GB300: fused GEMM(+bias+relu+capsule-normalize) + capsule routing
// N=20000, M=16 neighbors, FEAT=500, d=16, CAPS={8,7,6,5,4,3}, 5 routing iters
// GEMM: BM=64 tiles (wave-balanced), double-buffered, M-paired FFMA2.
// Routing: full fp16-operand datapath (z, u, ps) with split half2 accums.
// ---------------------------------------------------------------------------

#define NNODES 20000
#define MNBR   16
#define FEAT   500
#define OUTW   656

// scratch (device globals; no allocation allowed)
__device__ float  g_xnorm [NNODES * 128];  // fp32 normalized x
__device__ __half g_xnormh[NNODES * 128];  // fp16 mirror (neighbor gather)

// ---- packed f32x2 helpers (sm_103a FFMA2 via explicit PTX) ----------------
__device__ __forceinline__ unsigned long long f32x2_pack(float x, float y)
{
    unsigned long long r;
    asm("mov.b64 %0, {%1, %2};" : "=l"(r) : "f"(x), "f"(y));
    return r;
}
__device__ __forceinline__ void f32x2_unpack(unsigned long long v, float& x, float& y)
{
    asm("mov.b64 {%0, %1}, %2;" : "=f"(x), "=f"(y) : "l"(v));
}
__device__ __forceinline__ unsigned long long f32x2_fma(
    unsigned long long a, unsigned long long b, unsigned long long c)
{
    unsigned long long d;
    asm("fma.rn.f32x2 %0, %1, %2, %3;" : "=l"(d) : "l"(a), "l"(b), "l"(c));
    return d;
}
__device__ __forceinline__ __half2 u32_h2(uint32_t v)
{
    return *reinterpret_cast<__half2*>(&v);
}

// ---------------------------------------------------------------------------
// GEMM: val[M,N] = (relu?)(A[M,K] @ W[N,K]^T + bias[N])
// BM=64, BN=64, BKK=16, 256 threads; per-thread 4x4 microtile as 2 M-paired
// f32x2 accumulator rows. Double-buffered smem + register prefetch.
// ---------------------------------------------------------------------------
#define BM 64
#define BN 64
#define BKK 16

__device__ __forceinline__ float4 ldg4_guard(
    const float* __restrict__ P, int gr, int Rdim, int gc, int Kdim, int ld)
{
    float4 v = make_float4(0.f, 0.f, 0.f, 0.f);
    if (gr < Rdim) {
        if (gc + 3 < Kdim) {
            v = *reinterpret_cast<const float4*>(P + (size_t)gr * ld + gc);
        } else {
            const float* row = P + (size_t)gr * ld;
            if (gc + 0 < Kdim) v.x = row[gc + 0];
            if (gc + 1 < Kdim) v.y = row[gc + 1];
            if (gc + 2 < Kdim) v.z = row[gc + 2];
            if (gc + 3 < Kdim) v.w = row[gc + 3];
        }
    }
    return v;
}

template <bool WRITE_RAW>
__global__ void __launch_bounds__(256) gemm_norm_kernel(
    const float* __restrict__ A, int lda,
    const float* __restrict__ W, int ldw,
    const float* __restrict__ bias,
    float* __restrict__ rawOut, int ldo,
    float* __restrict__ xnorm,
    __half* __restrict__ xnormh,
    int Mdim, int Ndim, int Kdim)
{
    __shared__ float As[2][BKK][BM + 4];   // row stride 68 floats = 272B (16B-aligned)
    __shared__ float Ws[2][BKK][BN + 4];

    const int tid = threadIdx.x;
    const int tx = tid & 15;          // 0..15 -> 4 cols each
    const int ty = tid >> 4;          // 0..15 -> 4 rows each
    const int bm = blockIdx.y * BM;
    const int bn = blockIdx.x * BN;

    // loader lanes: one float4 of A and one of W per thread
    const int lr  = tid >> 2;         // 0..63
    const int lc4 = (tid & 3) * 4;

    // accp[p][j]: rows (ty*4+2p, ty*4+2p+1), col tx*4+j
    unsigned long long accp[2][4];
    const unsigned long long zz = f32x2_pack(0.f, 0.f);
#pragma unroll
    for (int p = 0; p < 2; ++p)
#pragma unroll
        for (int j = 0; j < 4; ++j) accp[p][j] = zz;

    const int nk = (Kdim + BKK - 1) / BKK;

    float4 av0, wv0;
    av0 = ldg4_guard(A, bm + lr, Mdim, 0 + lc4, Kdim, lda);
    wv0 = ldg4_guard(W, bn + lr, Ndim, 0 + lc4, Kdim, ldw);
    {
        As[0][lc4 + 0][lr] = av0.x; As[0][lc4 + 1][lr] = av0.y;
        As[0][lc4 + 2][lr] = av0.z; As[0][lc4 + 3][lr] = av0.w;
        Ws[0][lc4 + 0][lr] = wv0.x; Ws[0][lc4 + 1][lr] = wv0.y;
        Ws[0][lc4 + 2][lr] = wv0.z; Ws[0][lc4 + 3][lr] = wv0.w;
    }
    __syncthreads();

    for (int it = 0; it < nk; ++it) {
        const int buf = it & 1;
        if (it + 1 < nk) {
            int k0 = (it + 1) * BKK;
            av0 = ldg4_guard(A, bm + lr, Mdim, k0 + lc4, Kdim, lda);
            wv0 = ldg4_guard(W, bn + lr, Ndim, k0 + lc4, Kdim, ldw);
        }

#pragma unroll
        for (int kk = 0; kk < BKK; ++kk) {
            // a-pairs: rows ty*4..+3 -> 1x LDS.128 = 2 packed f32x2 (no movs)
            ulonglong2 ap01 = *reinterpret_cast<const ulonglong2*>(&As[buf][kk][ty * 4]);
            unsigned long long ap[2] = {ap01.x, ap01.y};
            // b: 1x LDS.128 + 4 dup movs
            float4 bv = *reinterpret_cast<const float4*>(&Ws[buf][kk][tx * 4]);
            unsigned long long bb[4];
            bb[0] = f32x2_pack(bv.x, bv.x);
            bb[1] = f32x2_pack(bv.y, bv.y);
            bb[2] = f32x2_pack(bv.z, bv.z);
            bb[3] = f32x2_pack(bv.w, bv.w);
#pragma unroll
            for (int p = 0; p < 2; ++p)
#pragma unroll
                for (int j = 0; j < 4; ++j)
                    accp[p][j] = f32x2_fma(ap[p], bb[j], accp[p][j]);
        }

        if (it + 1 < nk) {
            const int nbuf = buf ^ 1;
            As[nbuf][lc4 + 0][lr] = av0.x; As[nbuf][lc4 + 1][lr] = av0.y;
            As[nbuf][lc4 + 2][lr] = av0.z; As[nbuf][lc4 + 3][lr] = av0.w;
            Ws[nbuf][lc4 + 0][lr] = wv0.x; Ws[nbuf][lc4 + 1][lr] = wv0.y;
            Ws[nbuf][lc4 + 2][lr] = wv0.z; Ws[nbuf][lc4 + 3][lr] = wv0.w;
            __syncthreads();
        }
    }

    // ---- unpack row-paired accumulators ----
    float accf[4][4];
#pragma unroll
    for (int p = 0; p < 2; ++p)
#pragma unroll
        for (int j = 0; j < 4; ++j) {
            float lo, hi;
            f32x2_unpack(accp[p][j], lo, hi);
            accf[2 * p][j] = lo;
            accf[2 * p + 1][j] = hi;
        }

    // ---- epilogue: bias (+relu) + per-capsule L2 normalize ----
    const int gc0 = bn + tx * 4;
    float bvals[4];
#pragma unroll
    for (int j = 0; j < 4; ++j) bvals[j] = (gc0 + j < Ndim) ? bias[gc0 + j] : 0.f;

#pragma unroll
    for (int i = 0; i < 4; ++i) {
        int gr = bm + ty * 4 + i;
        float v[4];
        float ssq = 0.f;
#pragma unroll
        for (int j = 0; j < 4; ++j) {
            float val = (gc0 + j < Ndim) ? accf[i][j] + bvals[j] : 0.f;
            if (WRITE_RAW) val = fmaxf(val, 0.f);
            v[j] = val;
            ssq += val * val;
        }
        // capsule (16 cols) spans 4 adjacent lanes (tx aligned group of 4)
        ssq += __shfl_xor_sync(0xffffffffu, ssq, 1);
        ssq += __shfl_xor_sync(0xffffffffu, ssq, 2);
        float inv = 1.f / fmaxf(sqrtf(ssq), 1e-12f);
        if (gr < Mdim && gc0 < Ndim) {
            if (WRITE_RAW) {
                float4 o = make_float4(v[0], v[1], v[2], v[3]);
                *reinterpret_cast<float4*>(rawOut + (size_t)gr * ldo + gc0) = o;
            }
            float4 no = make_float4(v[0] * inv, v[1] * inv, v[2] * inv, v[3] * inv);
            *reinterpret_cast<float4*>(xnorm + (size_t)gr * Ndim + gc0) = no;
            __half2 h0 = __floats2half2_rn(no.x, no.y);
            __half2 h1 = __floats2half2_rn(no.z, no.w);
            uint2 hp;
            hp.x = *reinterpret_cast<uint32_t*>(&h0);
            hp.y = *reinterpret_cast<uint32_t*>(&h1);
            *reinterpret_cast<uint2*>(xnormh + (size_t)gr * Ndim + gc0) = hp;
        }
    }
}

// ---------------------------------------------------------------------------
// Routing (R14 winner, unchanged): one CTA per node, NT = 16*P threads.
//  Phase A: z packed fp16 regs; u = 2 LDS.128 fp16; 8 HFMA2 split-acc dot.
//  Phase B: fp16 ps (k-major, stride 24 halves) -> 1 LDS.128; byte_perm
//           broadcasts; 16 HFMA2 depth-4 split accumulators; fp32 reductions.
// ---------------------------------------------------------------------------
template <int K>
__global__ void __launch_bounds__((K > 4) ? 128 : 64, (K > 4) ? 8 : 16)
routing_kernel(
    const float*  __restrict__ xnorm,
    const __half* __restrict__ xnormh,
    const int*    __restrict__ nbid,
    float* __restrict__ outp)
{
    constexpr int P  = (K > 4) ? 8 : 4;
    constexpr int KD = K * 16;
    constexpr int Q  = K * 4;
    constexpr int UPH = 24;                // u row stride (halves): 48B rows
    constexpr int PSH = 24;                // ps row stride (halves): 48B rows

    const int n = blockIdx.x;
    const int tid = threadIdx.x;

    __shared__ __align__(16) __half uh[8 * UPH];
    __shared__ __align__(16) __half psh[8 * PSH];  // k-major: psh[k*PSH + m]
    __shared__ int nb[16];

    if (tid < 16) nb[tid] = __ldg(nbid + n * MNBR + tid);

    if (tid < Q) {
        float4 v = reinterpret_cast<const float4*>(xnorm + (size_t)n * KD)[tid];
        __half2 h0 = __floats2half2_rn(v.x, v.y);
        __half2 h1 = __floats2half2_rn(v.z, v.w);
        uint2 hp;
        hp.x = *reinterpret_cast<uint32_t*>(&h0);
        hp.y = *reinterpret_cast<uint32_t*>(&h1);
        *reinterpret_cast<uint2*>(uh + (tid >> 2) * UPH + (tid & 3) * 4) = hp;
    }
    __syncthreads();

    const int mA = tid / P;
    const int kA = tid & (P - 1);
    const bool validA = (kA < K);
    const int kAc = validA ? kA : (K - 1);
    uint4 zr0, zr1;
    {
        const uint4* rowA = reinterpret_cast<const uint4*>(
            xnormh + (size_t)nb[mA] * KD + kAc * 16);
        zr0 = __ldg(rowA);
        zr1 = __ldg(rowA + 1);
    }

    const int qB = tid >> 1;
    const int gB = tid & 1;
    const bool validB = (tid < 2 * Q);
    const int qc = validB ? qB : (Q - 1);
    const int kB = qc >> 2;
    uint2 zah[8];
#pragma unroll
    for (int j = 0; j < 8; ++j)
        zah[j] = __ldg(reinterpret_cast<const uint2*>(
            xnormh + (size_t)nb[8 * gB + j] * KD + qc * 4));
    float4 xs4 = __ldg(reinterpret_cast<const float4*>(xnorm + (size_t)n * KD) + qc);

#pragma unroll
    for (int t = 0; t < 5; ++t) {
        // ---- A: agreement p[m][k] = <z[m,k,:], u[k,:]> via HFMA2 ----
        float p;
        {
            const uint4* uptr = reinterpret_cast<const uint4*>(uh + kAc * UPH);
            uint4 u0 = uptr[0];
            uint4 u1 = uptr[1];
            __half2 za0 = __float2half2_rn(0.f);
            __half2 za1 = __float2half2_rn(0.f);
            za0 = __hfma2(u32_h2(zr0.x), u32_h2(u0.x), za0);
            za1 = __hfma2(u32_h2(zr0.y), u32_h2(u0.y), za1);
            za0 = __hfma2(u32_h2(zr0.z), u32_h2(u0.z), za0);
            za1 = __hfma2(u32_h2(zr0.w), u32_h2(u0.w), za1);
            za0 = __hfma2(u32_h2(zr1.x), u32_h2(u1.x), za0);
            za1 = __hfma2(u32_h2(zr1.y), u32_h2(u1.y), za1);
            za0 = __hfma2(u32_h2(zr1.z), u32_h2(u1.z), za0);
            za1 = __hfma2(u32_h2(zr1.w), u32_h2(u1.w), za1);
            float2 f0 = __half22float2(za0);
            float2 f1 = __half22float2(za1);
            float pv = (f0.x + f0.y) + (f1.x + f1.y);
            p = validA ? pv : -1e30f;
        }
        // softmax over capsules (no max-sub: |p|<=~1, padding exp -> 0)
        float e = __expf(p);
        float s = e;
        s += __shfl_xor_sync(0xffffffffu, s, 1);
        s += __shfl_xor_sync(0xffffffffu, s, 2);
        if (P == 8) s += __shfl_xor_sync(0xffffffffu, s, 4);
        float pr = __fdividef(e, s);
        if (validA) psh[kA * PSH + mA] = __float2half_rn(pr);
        __syncthreads();

        // ---- B: u[k][:] = xself + sum_m z[m][k][:] * p[m][k] via HFMA2 ----
        uint4 pmv = *reinterpret_cast<const uint4*>(psh + kB * PSH + 8 * gB);
        uint32_t pmw[4] = {pmv.x, pmv.y, pmv.z, pmv.w};
        __half2 aA_lo = __float2half2_rn(0.f), aA_hi = __float2half2_rn(0.f);
        __half2 aB_lo = __float2half2_rn(0.f), aB_hi = __float2half2_rn(0.f);
#pragma unroll
        for (int w = 0; w < 4; ++w) {
            uint32_t lo_b = __byte_perm(pmw[w], pmw[w], 0x1010);
            uint32_t hi_b = __byte_perm(pmw[w], pmw[w], 0x3232);
            __half2 pm0 = u32_h2(lo_b);
            __half2 pm1 = u32_h2(hi_b);
            int j0 = 2 * w, j1 = 2 * w + 1;
            if (w < 2) {
                aA_lo = __hfma2(u32_h2(zah[j0].x), pm0, aA_lo);
                aA_hi = __hfma2(u32_h2(zah[j0].y), pm0, aA_hi);
                aA_lo = __hfma2(u32_h2(zah[j1].x), pm1, aA_lo);
                aA_hi = __hfma2(u32_h2(zah[j1].y), pm1, aA_hi);
            } else {
                aB_lo = __hfma2(u32_h2(zah[j0].x), pm0, aB_lo);
                aB_hi = __hfma2(u32_h2(zah[j0].y), pm0, aB_hi);
                aB_lo = __hfma2(u32_h2(zah[j1].x), pm1, aB_lo);
                aB_hi = __hfma2(u32_h2(zah[j1].y), pm1, aB_hi);
            }
        }
        float2 fA_lo = __half22float2(aA_lo);
        float2 fA_hi = __half22float2(aA_hi);
        float2 fB_lo = __half22float2(aB_lo);
        float2 fB_hi = __half22float2(aB_hi);
        float4 acc;
        acc.x = fA_lo.x + fB_lo.x;
        acc.y = fA_lo.y + fB_lo.y;
        acc.z = fA_hi.x + fB_hi.x;
        acc.w = fA_hi.y + fB_hi.y;

        acc.x += __shfl_xor_sync(0xffffffffu, acc.x, 1);
        acc.y += __shfl_xor_sync(0xffffffffu, acc.y, 1);
        acc.z += __shfl_xor_sync(0xffffffffu, acc.z, 1);
        acc.w += __shfl_xor_sync(0xffffffffu, acc.w, 1);
        acc.x += xs4.x; acc.y += xs4.y; acc.z += xs4.z; acc.w += xs4.w;

        if (t < 4) {
            float sq = acc.x * acc.x + acc.y * acc.y + acc.z * acc.z + acc.w * acc.w;
            sq += __shfl_xor_sync(0xffffffffu, sq, 2);
            sq += __shfl_xor_sync(0xffffffffu, sq, 4);
            float inv = rsqrtf(fmaxf(sq, 1e-24f));
            if (validB && gB == 0) {
                __half2 h0 = __floats2half2_rn(acc.x * inv, acc.y * inv);
                __half2 h1 = __floats2half2_rn(acc.z * inv, acc.w * inv);
                uint2 hp;
                hp.x = *reinterpret_cast<uint32_t*>(&h0);
                hp.y = *reinterpret_cast<uint32_t*>(&h1);
                *reinterpret_cast<uint2*>(uh + kB * UPH + (qB & 3) * 4) = hp;
            }
            __syncthreads();
        } else if (validB && gB == 0) {
            float4 o = make_float4(fmaxf(acc.x, 0.f), fmaxf(acc.y, 0.f),
                                   fmaxf(acc.z, 0.f), fmaxf(acc.w, 0.f));
            *reinterpret_cast<float4*>(outp + (size_t)n * OUTW + qB * 4) = o;
        }
    }
}

// ---------------------------------------------------------------------------
// host orchestration
// ---------------------------------------------------------------------------
extern "C" void kernel_launch(void* const* d_in, const int* in_sizes, int n_in,
                              void* d_out, int out_size)
{
    (void)in_sizes; (void)n_in; (void)out_size;
    const float* feature = (const float*)d_in[0];
    const int*   nbid    = (const int*)d_in[1];
    const float* pca_w   = (const float*)d_in[2];
    const float* pca_b   = (const float*)d_in[3];
    const float* W[6]  = {nullptr, (const float*)d_in[4], (const float*)d_in[6],
                          (const float*)d_in[8], (const float*)d_in[10], (const float*)d_in[12]};
    const float* Bb[6] = {nullptr, (const float*)d_in[5], (const float*)d_in[7],
                          (const float*)d_in[9], (const float*)d_in[11], (const float*)d_in[13]};
    float* out = (float*)d_out;

    static const int caps[6]   = {8, 7, 6, 5, 4, 3};
    static const int coloff[7] = {0, 128, 256, 368, 464, 544, 608};

    float* xnorm;
    __half* xnormh;
    cudaGetSymbolAddress((void**)&xnorm,  g_xnorm);
    cudaGetSymbolAddress((void**)&xnormh, g_xnormh);

    const int mblocks = (NNODES + BM - 1) / BM;   // 313

    // PCA: x0 = relu(feature @ pca_w.T + pca_b) -> out[:,0:128] + xnorm(+h)
    {
        dim3 grid((128 + BN - 1) / BN, mblocks);
        gemm_norm_kernel<true><<<grid, 256>>>(feature, FEAT, pca_w, FEAT, pca_b,
                                              out, OUTW, xnorm, xnormh,
                                              NNODES, 128, FEAT);
    }

    for (int i = 0; i < 6; ++i) {
        int k = caps[i];
        int kd = k * 16;
        if (i > 0) {
            int fin = caps[i - 1] * 16;
            dim3 grid((kd + BN - 1) / BN, mblocks);
            gemm_norm_kernel<false><<<grid, 256>>>(out + coloff[i], OUTW,
                                                   W[i], fin, Bb[i],
                                                   nullptr, 0, xnorm, xnormh,
                                                   NNODES, kd, fin);
        }
        float* dst = out + coloff[i + 1];
        switch (k) {
            case 8: routing_kernel<8><<<NNODES, 128>>>(xnorm, xnormh, nbid, dst); break;
            case 7: routing_kernel<7><<<NNODES, 128>>>(xnorm, xnormh, nbid, dst); break;
            case 6: routing_kernel<6><<<NNODES, 128>>>(xnorm, xnormh, nbid, dst); break;
            case 5: routing_kernel<5><<<NNODES, 128>>>(xnorm, xnormh, nbid, dst); break;
            case 4: routing_kernel<4><<<NNODES, 64>>>(xnorm, xnormh, nbid, dst); break;
            case 3: routing_kernel<3><<<NNODES, 64>>>(xnorm, xnormh, nbid, dst); break;
        }
    }
}

// round 17
// speedup vs baseline: 1.1603x; 1.1603x over previous
#include <cuda_runtime.h>
#include <cuda_fp16.h>
#include <cstdint>

// ---------------------------------------------------------------------------
// DisenGCN on GB300: HMMA GEMM (fp16-split, fp32-exact) + capsule routing
// N=20000, M=16 neighbors, FEAT=500, d=16, CAPS={8,7,6,5,4,3}, 5 routing iters
// GEMM: mma.sync.m16n8k16 with 2-term fp16 split (hh + hl + lh), fused
// bias/relu/capsule-normalize epilogue. Routing: fp16-operand datapath (R14).
// ---------------------------------------------------------------------------

#define NNODES 20000
#define MNBR   16
#define FEAT   500
#define OUTW   656

// scratch (device globals; no allocation allowed)
__device__ float  g_xnorm [NNODES * 128];  // fp32 normalized x
__device__ __half g_xnormh[NNODES * 128];  // fp16 mirror (neighbor gather)

__device__ __forceinline__ __half2 u32_h2(uint32_t v)
{
    return *reinterpret_cast<__half2*>(&v);
}

// ---------------------------------------------------------------------------
// HMMA GEMM: val[M,N] = (relu?)(A[M,K] @ W[N,K]^T + bias[N])
//   epilogue: per-16-col-capsule L2 normalize -> xnorm (fp32) + xnormh (fp16)
// BM=128, BN=64, BK=16, 256 threads (8 warps as 4x2), warp tile 32x32.
// fp16 split: x = h + l (both fp16); C += Ah*Bh + Ah*Bl + Al*Bh (fp32 accum).
// ---------------------------------------------------------------------------
#define BM 128
#define BN 64
#define BKK 16
#define SA 24   // smem row stride in halves (48B rows; frag banks conflict-free)

#define MMA16816(C, A, B) \
    asm volatile("mma.sync.aligned.m16n8k16.row.col.f32.f16.f16.f32 " \
        "{%0,%1,%2,%3},{%4,%5,%6,%7},{%8,%9},{%0,%1,%2,%3};" \
        : "+f"((C)[0]), "+f"((C)[1]), "+f"((C)[2]), "+f"((C)[3]) \
        : "r"((A)[0]), "r"((A)[1]), "r"((A)[2]), "r"((A)[3]), \
          "r"((B)[0]), "r"((B)[1]))

__device__ __forceinline__ float4 ldg4_guard(
    const float* __restrict__ P, int gr, int Rdim, int gc, int Kdim, int ld)
{
    float4 v = make_float4(0.f, 0.f, 0.f, 0.f);
    if (gr < Rdim) {
        if (gc + 3 < Kdim) {
            v = *reinterpret_cast<const float4*>(P + (size_t)gr * ld + gc);
        } else {
            const float* row = P + (size_t)gr * ld;
            if (gc + 0 < Kdim) v.x = row[gc + 0];
            if (gc + 1 < Kdim) v.y = row[gc + 1];
            if (gc + 2 < Kdim) v.z = row[gc + 2];
            if (gc + 3 < Kdim) v.w = row[gc + 3];
        }
    }
    return v;
}

// split float4 into fp16 hi + fp16 residual, store 4 halves each (uint2)
__device__ __forceinline__ void split_store(__half* ph, __half* pl, float4 v)
{
    __half2 h01 = __floats2half2_rn(v.x, v.y);
    __half2 h23 = __floats2half2_rn(v.z, v.w);
    float2 f01 = __half22float2(h01);
    float2 f23 = __half22float2(h23);
    __half2 l01 = __floats2half2_rn(v.x - f01.x, v.y - f01.y);
    __half2 l23 = __floats2half2_rn(v.z - f23.x, v.w - f23.y);
    uint2 hp, lp;
    hp.x = *reinterpret_cast<uint32_t*>(&h01);
    hp.y = *reinterpret_cast<uint32_t*>(&h23);
    lp.x = *reinterpret_cast<uint32_t*>(&l01);
    lp.y = *reinterpret_cast<uint32_t*>(&l23);
    *reinterpret_cast<uint2*>(ph) = hp;
    *reinterpret_cast<uint2*>(pl) = lp;
}

__device__ __forceinline__ uint32_t lds32(const __half* p)
{
    return *reinterpret_cast<const uint32_t*>(p);
}

template <bool WRITE_RAW>
__global__ void __launch_bounds__(256) gemm_mma_kernel(
    const float* __restrict__ A, int lda,
    const float* __restrict__ W, int ldw,
    const float* __restrict__ bias,
    float* __restrict__ rawOut, int ldo,
    float* __restrict__ xnorm,
    __half* __restrict__ xnormh,
    int Mdim, int Ndim, int Kdim)
{
    __shared__ __align__(16) __half Ah[2][BM * SA];
    __shared__ __align__(16) __half Al[2][BM * SA];
    __shared__ __align__(16) __half Wh[2][BN * SA];
    __shared__ __align__(16) __half Wl[2][BN * SA];

    const int tid  = threadIdx.x;
    const int lane = tid & 31;
    const int warp = tid >> 5;
    const int wm   = warp >> 1;          // 0..3 -> 32 rows each
    const int wn   = warp & 1;           // 0..1 -> 32 cols each
    const int g    = lane >> 2;          // 0..7
    const int q    = lane & 3;           // 0..3
    const int bm   = blockIdx.y * BM;
    const int bn   = blockIdx.x * BN;

    // loader lanes
    const int ar0 = tid >> 2;            // A rows (2 float4 per thread)
    const int ar1 = ar0 + 64;
    const int ac4 = (tid & 3) * 4;
    const int wr  = tid >> 2;            // W row (1 float4 per thread)

    float c[2][4][4];
#pragma unroll
    for (int mt = 0; mt < 2; ++mt)
#pragma unroll
        for (int nt = 0; nt < 4; ++nt)
#pragma unroll
            for (int i = 0; i < 4; ++i) c[mt][nt][i] = 0.f;

    const int nk = (Kdim + BKK - 1) / BKK;

    float4 av0, av1, wv0;
    av0 = ldg4_guard(A, bm + ar0, Mdim, 0 + ac4, Kdim, lda);
    av1 = ldg4_guard(A, bm + ar1, Mdim, 0 + ac4, Kdim, lda);
    wv0 = ldg4_guard(W, bn + wr,  Ndim, 0 + ac4, Kdim, ldw);
    split_store(&Ah[0][ar0 * SA + ac4], &Al[0][ar0 * SA + ac4], av0);
    split_store(&Ah[0][ar1 * SA + ac4], &Al[0][ar1 * SA + ac4], av1);
    split_store(&Wh[0][wr  * SA + ac4], &Wl[0][wr  * SA + ac4], wv0);
    __syncthreads();

    for (int it = 0; it < nk; ++it) {
        const int buf = it & 1;
        if (it + 1 < nk) {
            int k0 = (it + 1) * BKK;
            av0 = ldg4_guard(A, bm + ar0, Mdim, k0 + ac4, Kdim, lda);
            av1 = ldg4_guard(A, bm + ar1, Mdim, k0 + ac4, Kdim, lda);
            wv0 = ldg4_guard(W, bn + wr,  Ndim, k0 + ac4, Kdim, ldw);
        }

        // ---- fragment loads (conflict-free LDS.32) ----
        uint32_t fah[2][4], fal[2][4], fbh[4][2], fbl[4][2];
        const __half* pAh = Ah[buf];
        const __half* pAl = Al[buf];
        const __half* pWh = Wh[buf];
        const __half* pWl = Wl[buf];
#pragma unroll
        for (int mt = 0; mt < 2; ++mt) {
            int r0 = (wm * 32 + mt * 16 + g) * SA + 2 * q;
            int r8 = r0 + 8 * SA;
            fah[mt][0] = lds32(pAh + r0);
            fah[mt][1] = lds32(pAh + r8);
            fah[mt][2] = lds32(pAh + r0 + 8);
            fah[mt][3] = lds32(pAh + r8 + 8);
            fal[mt][0] = lds32(pAl + r0);
            fal[mt][1] = lds32(pAl + r8);
            fal[mt][2] = lds32(pAl + r0 + 8);
            fal[mt][3] = lds32(pAl + r8 + 8);
        }
#pragma unroll
        for (int nt = 0; nt < 4; ++nt) {
            int n0 = (wn * 32 + nt * 8 + g) * SA + 2 * q;
            fbh[nt][0] = lds32(pWh + n0);
            fbh[nt][1] = lds32(pWh + n0 + 8);
            fbl[nt][0] = lds32(pWl + n0);
            fbl[nt][1] = lds32(pWl + n0 + 8);
        }

        // ---- 3-product split MMA: hh + hl + lh ----
#pragma unroll
        for (int mt = 0; mt < 2; ++mt)
#pragma unroll
            for (int nt = 0; nt < 4; ++nt) {
                MMA16816(c[mt][nt], fah[mt], fbh[nt]);
                MMA16816(c[mt][nt], fah[mt], fbl[nt]);
                MMA16816(c[mt][nt], fal[mt], fbh[nt]);
            }

        if (it + 1 < nk) {
            const int nbuf = buf ^ 1;
            split_store(&Ah[nbuf][ar0 * SA + ac4], &Al[nbuf][ar0 * SA + ac4], av0);
            split_store(&Ah[nbuf][ar1 * SA + ac4], &Al[nbuf][ar1 * SA + ac4], av1);
            split_store(&Wh[nbuf][wr  * SA + ac4], &Wl[nbuf][wr  * SA + ac4], wv0);
            __syncthreads();
        }
    }

    // ---- epilogue: bias (+relu) + per-capsule L2 normalize ----
    float2 bv[4];
#pragma unroll
    for (int nt = 0; nt < 4; ++nt) {
        int gc = bn + wn * 32 + nt * 8 + 2 * q;
        bv[nt].x = (gc + 0 < Ndim) ? bias[gc + 0] : 0.f;
        bv[nt].y = (gc + 1 < Ndim) ? bias[gc + 1] : 0.f;
    }

#pragma unroll
    for (int mt = 0; mt < 2; ++mt) {
#pragma unroll
        for (int hh = 0; hh < 2; ++hh) {
            int gr = bm + wm * 32 + mt * 16 + g + 8 * hh;
            float v[8];
#pragma unroll
            for (int nt = 0; nt < 4; ++nt) {
                float a = c[mt][nt][2 * hh + 0] + bv[nt].x;
                float b = c[mt][nt][2 * hh + 1] + bv[nt].y;
                if (WRITE_RAW) { a = fmaxf(a, 0.f); b = fmaxf(b, 0.f); }
                v[2 * nt + 0] = a;
                v[2 * nt + 1] = b;
            }
            // capsule ssq: capsule A = n-tiles 0,1; capsule B = n-tiles 2,3
            float ssqA = v[0]*v[0] + v[1]*v[1] + v[2]*v[2] + v[3]*v[3];
            float ssqB = v[4]*v[4] + v[5]*v[5] + v[6]*v[6] + v[7]*v[7];
            ssqA += __shfl_xor_sync(0xffffffffu, ssqA, 1);
            ssqA += __shfl_xor_sync(0xffffffffu, ssqA, 2);
            ssqB += __shfl_xor_sync(0xffffffffu, ssqB, 1);
            ssqB += __shfl_xor_sync(0xffffffffu, ssqB, 2);
            float invA = 1.f / fmaxf(sqrtf(ssqA), 1e-12f);
            float invB = 1.f / fmaxf(sqrtf(ssqB), 1e-12f);
            if (gr < Mdim) {
#pragma unroll
                for (int nt = 0; nt < 4; ++nt) {
                    int gc = bn + wn * 32 + nt * 8 + 2 * q;
                    if (gc + 1 >= Ndim) continue;
                    float inv = (nt < 2) ? invA : invB;
                    float n0 = v[2 * nt + 0] * inv;
                    float n1 = v[2 * nt + 1] * inv;
                    if (WRITE_RAW) {
                        float2 o = make_float2(v[2 * nt], v[2 * nt + 1]);
                        *reinterpret_cast<float2*>(rawOut + (size_t)gr * ldo + gc) = o;
                    }
                    *reinterpret_cast<float2*>(xnorm + (size_t)gr * Ndim + gc) =
                        make_float2(n0, n1);
                    __half2 hn = __floats2half2_rn(n0, n1);
                    *reinterpret_cast<uint32_t*>(xnormh + (size_t)gr * Ndim + gc) =
                        *reinterpret_cast<uint32_t*>(&hn);
                }
            }
        }
    }
}

// ---------------------------------------------------------------------------
// Routing (R14 winner, unchanged): one CTA per node, NT = 16*P threads.
//  Phase A: z packed fp16 regs; u = 2 LDS.128 fp16; 8 HFMA2 split-acc dot.
//  Phase B: fp16 ps (k-major, stride 24 halves) -> 1 LDS.128; byte_perm
//           broadcasts; 16 HFMA2 depth-4 split accumulators; fp32 reductions.
// ---------------------------------------------------------------------------
template <int K>
__global__ void __launch_bounds__((K > 4) ? 128 : 64, (K > 4) ? 8 : 16)
routing_kernel(
    const float*  __restrict__ xnorm,
    const __half* __restrict__ xnormh,
    const int*    __restrict__ nbid,
    float* __restrict__ outp)
{
    constexpr int P  = (K > 4) ? 8 : 4;
    constexpr int KD = K * 16;
    constexpr int Q  = K * 4;
    constexpr int UPH = 24;                // u row stride (halves): 48B rows
    constexpr int PSH = 24;                // ps row stride (halves): 48B rows

    const int n = blockIdx.x;
    const int tid = threadIdx.x;

    __shared__ __align__(16) __half uh[8 * UPH];
    __shared__ __align__(16) __half psh[8 * PSH];  // k-major: psh[k*PSH + m]
    __shared__ int nb[16];

    if (tid < 16) nb[tid] = __ldg(nbid + n * MNBR + tid);

    if (tid < Q) {
        float4 v = reinterpret_cast<const float4*>(xnorm + (size_t)n * KD)[tid];
        __half2 h0 = __floats2half2_rn(v.x, v.y);
        __half2 h1 = __floats2half2_rn(v.z, v.w);
        uint2 hp;
        hp.x = *reinterpret_cast<uint32_t*>(&h0);
        hp.y = *reinterpret_cast<uint32_t*>(&h1);
        *reinterpret_cast<uint2*>(uh + (tid >> 2) * UPH + (tid & 3) * 4) = hp;
    }
    __syncthreads();

    const int mA = tid / P;
    const int kA = tid & (P - 1);
    const bool validA = (kA < K);
    const int kAc = validA ? kA : (K - 1);
    uint4 zr0, zr1;
    {
        const uint4* rowA = reinterpret_cast<const uint4*>(
            xnormh + (size_t)nb[mA] * KD + kAc * 16);
        zr0 = __ldg(rowA);
        zr1 = __ldg(rowA + 1);
    }

    const int qB = tid >> 1;
    const int gB = tid & 1;
    const bool validB = (tid < 2 * Q);
    const int qc = validB ? qB : (Q - 1);
    const int kB = qc >> 2;
    uint2 zah[8];
#pragma unroll
    for (int j = 0; j < 8; ++j)
        zah[j] = __ldg(reinterpret_cast<const uint2*>(
            xnormh + (size_t)nb[8 * gB + j] * KD + qc * 4));
    float4 xs4 = __ldg(reinterpret_cast<const float4*>(xnorm + (size_t)n * KD) + qc);

#pragma unroll
    for (int t = 0; t < 5; ++t) {
        // ---- A: agreement p[m][k] = <z[m,k,:], u[k,:]> via HFMA2 ----
        float p;
        {
            const uint4* uptr = reinterpret_cast<const uint4*>(uh + kAc * UPH);
            uint4 u0 = uptr[0];
            uint4 u1 = uptr[1];
            __half2 za0 = __float2half2_rn(0.f);
            __half2 za1 = __float2half2_rn(0.f);
            za0 = __hfma2(u32_h2(zr0.x), u32_h2(u0.x), za0);
            za1 = __hfma2(u32_h2(zr0.y), u32_h2(u0.y), za1);
            za0 = __hfma2(u32_h2(zr0.z), u32_h2(u0.z), za0);
            za1 = __hfma2(u32_h2(zr0.w), u32_h2(u0.w), za1);
            za0 = __hfma2(u32_h2(zr1.x), u32_h2(u1.x), za0);
            za1 = __hfma2(u32_h2(zr1.y), u32_h2(u1.y), za1);
            za0 = __hfma2(u32_h2(zr1.z), u32_h2(u1.z), za0);
            za1 = __hfma2(u32_h2(zr1.w), u32_h2(u1.w), za1);
            float2 f0 = __half22float2(za0);
            float2 f1 = __half22float2(za1);
            float pv = (f0.x + f0.y) + (f1.x + f1.y);
            p = validA ? pv : -1e30f;
        }
        // softmax over capsules (no max-sub: |p|<=~1, padding exp -> 0)
        float e = __expf(p);
        float s = e;
        s += __shfl_xor_sync(0xffffffffu, s, 1);
        s += __shfl_xor_sync(0xffffffffu, s, 2);
        if (P == 8) s += __shfl_xor_sync(0xffffffffu, s, 4);
        float pr = __fdividef(e, s);
        if (validA) psh[kA * PSH + mA] = __float2half_rn(pr);
        __syncthreads();

        // ---- B: u[k][:] = xself + sum_m z[m][k][:] * p[m][k] via HFMA2 ----
        uint4 pmv = *reinterpret_cast<const uint4*>(psh + kB * PSH + 8 * gB);
        uint32_t pmw[4] = {pmv.x, pmv.y, pmv.z, pmv.w};
        __half2 aA_lo = __float2half2_rn(0.f), aA_hi = __float2half2_rn(0.f);
        __half2 aB_lo = __float2half2_rn(0.f), aB_hi = __float2half2_rn(0.f);
#pragma unroll
        for (int w = 0; w < 4; ++w) {
            uint32_t lo_b = __byte_perm(pmw[w], pmw[w], 0x1010);
            uint32_t hi_b = __byte_perm(pmw[w], pmw[w], 0x3232);
            __half2 pm0 = u32_h2(lo_b);
            __half2 pm1 = u32_h2(hi_b);
            int j0 = 2 * w, j1 = 2 * w + 1;
            if (w < 2) {
                aA_lo = __hfma2(u32_h2(zah[j0].x), pm0, aA_lo);
                aA_hi = __hfma2(u32_h2(zah[j0].y), pm0, aA_hi);
                aA_lo = __hfma2(u32_h2(zah[j1].x), pm1, aA_lo);
                aA_hi = __hfma2(u32_h2(zah[j1].y), pm1, aA_hi);
            } else {
                aB_lo = __hfma2(u32_h2(zah[j0].x), pm0, aB_lo);
                aB_hi = __hfma2(u32_h2(zah[j0].y), pm0, aB_hi);
                aB_lo = __hfma2(u32_h2(zah[j1].x), pm1, aB_lo);
                aB_hi = __hfma2(u32_h2(zah[j1].y), pm1, aB_hi);
            }
        }
        float2 fA_lo = __half22float2(aA_lo);
        float2 fA_hi = __half22float2(aA_hi);
        float2 fB_lo = __half22float2(aB_lo);
        float2 fB_hi = __half22float2(aB_hi);
        float4 acc;
        acc.x = fA_lo.x + fB_lo.x;
        acc.y = fA_lo.y + fB_lo.y;
        acc.z = fA_hi.x + fB_hi.x;
        acc.w = fA_hi.y + fB_hi.y;

        acc.x += __shfl_xor_sync(0xffffffffu, acc.x, 1);
        acc.y += __shfl_xor_sync(0xffffffffu, acc.y, 1);
        acc.z += __shfl_xor_sync(0xffffffffu, acc.z, 1);
        acc.w += __shfl_xor_sync(0xffffffffu, acc.w, 1);
        acc.x += xs4.x; acc.y += xs4.y; acc.z += xs4.z; acc.w += xs4.w;

        if (t < 4) {
            float sq = acc.x * acc.x + acc.y * acc.y + acc.z * acc.z + acc.w * acc.w;
            sq += __shfl_xor_sync(0xffffffffu, sq, 2);
            sq += __shfl_xor_sync(0xffffffffu, sq, 4);
            float inv = rsqrtf(fmaxf(sq, 1e-24f));
            if (validB && gB == 0) {
                __half2 h0 = __floats2half2_rn(acc.x * inv, acc.y * inv);
                __half2 h1 = __floats2half2_rn(acc.z * inv, acc.w * inv);
                uint2 hp;
                hp.x = *reinterpret_cast<uint32_t*>(&h0);
                hp.y = *reinterpret_cast<uint32_t*>(&h1);
                *reinterpret_cast<uint2*>(uh + kB * UPH + (qB & 3) * 4) = hp;
            }
            __syncthreads();
        } else if (validB && gB == 0) {
            float4 o = make_float4(fmaxf(acc.x, 0.f), fmaxf(acc.y, 0.f),
                                   fmaxf(acc.z, 0.f), fmaxf(acc.w, 0.f));
            *reinterpret_cast<float4*>(outp + (size_t)n * OUTW + qB * 4) = o;
        }
    }
}

// ---------------------------------------------------------------------------
// host orchestration
// ---------------------------------------------------------------------------
extern "C" void kernel_launch(void* const* d_in, const int* in_sizes, int n_in,
                              void* d_out, int out_size)
{
    (void)in_sizes; (void)n_in; (void)out_size;
    const float* feature = (const float*)d_in[0];
    const int*   nbid    = (const int*)d_in[1];
    const float* pca_w   = (const float*)d_in[2];
    const float* pca_b   = (const float*)d_in[3];
    const float* W[6]  = {nullptr, (const float*)d_in[4], (const float*)d_in[6],
                          (const float*)d_in[8], (const float*)d_in[10], (const float*)d_in[12]};
    const float* Bb[6] = {nullptr, (const float*)d_in[5], (const float*)d_in[7],
                          (const float*)d_in[9], (const float*)d_in[11], (const float*)d_in[13]};
    float* out = (float*)d_out;

    static const int caps[6]   = {8, 7, 6, 5, 4, 3};
    static const int coloff[7] = {0, 128, 256, 368, 464, 544, 608};

    float* xnorm;
    __half* xnormh;
    cudaGetSymbolAddress((void**)&xnorm,  g_xnorm);
    cudaGetSymbolAddress((void**)&xnormh, g_xnormh);

    const int mblocks = (NNODES + BM - 1) / BM;   // 157

    // PCA: x0 = relu(feature @ pca_w.T + pca_b) -> out[:,0:128] + xnorm(+h)
    {
        dim3 grid((128 + BN - 1) / BN, mblocks);
        gemm_mma_kernel<true><<<grid, 256>>>(feature, FEAT, pca_w, FEAT, pca_b,
                                             out, OUTW, xnorm, xnormh,
                                             NNODES, 128, FEAT);
    }

    for (int i = 0; i < 6; ++i) {
        int k = caps[i];
        int kd = k * 16;
        if (i > 0) {
            int fin = caps[i - 1] * 16;
            dim3 grid((kd + BN - 1) / BN, mblocks);
            gemm_mma_kernel<false><<<grid, 256>>>(out + coloff[i], OUTW,
                                                  W[i], fin, Bb[i],
                                                  nullptr, 0, xnorm, xnormh,
                                                  NNODES, kd, fin);
        }
        float* dst = out + coloff[i + 1];
        switch (k) {
            case 8: routing_kernel<8><<<NNODES, 128>>>(xnorm, xnormh, nbid, dst); break;
            case 7: routing_kernel<7><<<NNODES, 128>>>(xnorm, xnormh, nbid, dst); break;
            case 6: routing_kernel<6><<<NNODES, 128>>>(xnorm, xnormh, nbid, dst); break;
            case 5: routing_kernel<5><<<NNODES, 128>>>(xnorm, xnormh, nbid, dst); break;
            case 4: routing_kernel<4><<<NNODES, 64>>>(xnorm, xnormh, nbid, dst); break;
            case 3: routing_kernel<3><<<NNODES, 64>>>(xnorm, xnormh, nbid, dst); break;
        }
    }
}